// round 1
// baseline (speedup 1.0000x reference)
#include <cuda_runtime.h>
#include <math.h>
#include <stdint.h>

// Problem-fixed shapes (from setup_inputs): N=100000, C=256, H=128, K=64, E=1600000
#define NN   100000
#define EE   1600000
#define ETOT (EE + NN)
#define CDIM 256
#define HDIM 128
#define KOUT 64

// ---------------- device scratch (static, no allocation) ----------------
__device__ int   g_deg[NN];
__device__ int   g_incl[NN];
__device__ int   g_bsums[256];
__device__ int   g_rowptr[NN + 1];
__device__ int   g_pos[NN];
__device__ int   g_col[ETOT];
__device__ float g_h1[NN * HDIM];
__device__ float g_x1[NN * HDIM];
__device__ float g_h2[NN * KOUT];
__device__ float g_s1[NN], g_d1[NN], g_s2[NN], g_d2[NN];

// ---------------- CSR build ----------------
__global__ void init_deg_kernel(int* deg, int n) {
    int i = blockIdx.x * blockDim.x + threadIdx.x;
    if (i < n) deg[i] = 1;  // self-loop
}

__global__ void hist_kernel(const int* __restrict__ dst, int* deg, int e) {
    int i = blockIdx.x * blockDim.x + threadIdx.x;
    if (i < e) atomicAdd(&deg[dst[i]], 1);
}

// block-wise inclusive scan (1024 elems / block)
__global__ void scan_block_kernel(const int* __restrict__ deg, int* incl, int* bsums, int n) {
    __shared__ int sh[1024];
    int t = threadIdx.x;
    int gid = blockIdx.x * 1024 + t;
    sh[t] = (gid < n) ? deg[gid] : 0;
    __syncthreads();
    #pragma unroll
    for (int off = 1; off < 1024; off <<= 1) {
        int v = (t >= off) ? sh[t - off] : 0;
        __syncthreads();
        sh[t] += v;
        __syncthreads();
    }
    if (gid < n) incl[gid] = sh[t];
    if (t == 1023) bsums[blockIdx.x] = sh[t];
}

__global__ void scan_bsums_kernel(int* bsums, int nb) {
    if (threadIdx.x == 0 && blockIdx.x == 0) {
        int run = 0;
        for (int b = 0; b < nb; b++) { int v = bsums[b]; bsums[b] = run; run += v; }
    }
}

__global__ void finalize_rowptr_kernel(const int* __restrict__ incl, const int* __restrict__ bsums,
                                       int* rowptr, int n) {
    int gid = blockIdx.x * blockDim.x + threadIdx.x;
    if (gid < n) rowptr[gid + 1] = incl[gid] + bsums[gid >> 10];
    if (gid == 0) rowptr[0] = 0;
}

__global__ void copy_pos_kernel(const int* __restrict__ rowptr, int* pos, int n) {
    int i = blockIdx.x * blockDim.x + threadIdx.x;
    if (i < n) pos[i] = rowptr[i];
}

__global__ void scatter_kernel(const int* __restrict__ srcv, const int* __restrict__ dstv,
                               int* pos, int* colv, int e) {
    int i = blockIdx.x * blockDim.x + threadIdx.x;
    if (i < e) {
        int p = atomicAdd(&pos[dstv[i]], 1);
        colv[p] = srcv[i];
    }
}

__global__ void selfloop_kernel(int* pos, int* colv, int n) {
    int i = blockIdx.x * blockDim.x + threadIdx.x;
    if (i < n) {
        int p = atomicAdd(&pos[i], 1);
        colv[p] = i;
    }
}

// ---------------- tiled SGEMM: C[M x NDIM] = A[M x KD] * B[KD x NDIM] ----------------
// Full N covered by one block column (NDIM == BN), grid only over M.
template <int NDIM, int KD, int TN>
__global__ __launch_bounds__(256) void sgemm_kernel(const float* __restrict__ A,
                                                    const float* __restrict__ B,
                                                    float* __restrict__ Cmat, int M) {
    constexpr int BM = 128, BK = 16, TM = 8, BN = NDIM;
    __shared__ float As[BK][BM];
    __shared__ float Bs[BK][BN];
    int tid = threadIdx.x;
    int tx = tid % (BN / TN);
    int ty = tid / (BN / TN);
    int rowBase = blockIdx.x * BM;
    float acc[TM][TN];
    #pragma unroll
    for (int i = 0; i < TM; i++)
        #pragma unroll
        for (int j = 0; j < TN; j++) acc[i][j] = 0.f;

    for (int k0 = 0; k0 < KD; k0 += BK) {
        // load A tile (BM x BK), transpose into As[k][m]
        for (int lin = tid; lin < BM * BK / 4; lin += 256) {
            int r = lin / (BK / 4);
            int kq = (lin % (BK / 4)) * 4;
            float4 v = make_float4(0.f, 0.f, 0.f, 0.f);
            int gr = rowBase + r;
            if (gr < M) v = *reinterpret_cast<const float4*>(A + (size_t)gr * KD + k0 + kq);
            As[kq + 0][r] = v.x;
            As[kq + 1][r] = v.y;
            As[kq + 2][r] = v.z;
            As[kq + 3][r] = v.w;
        }
        // load B tile (BK x BN)
        for (int lin = tid; lin < BK * BN / 4; lin += 256) {
            int r = lin / (BN / 4);
            int c = (lin % (BN / 4)) * 4;
            *reinterpret_cast<float4*>(&Bs[r][c]) =
                *reinterpret_cast<const float4*>(B + (size_t)(k0 + r) * NDIM + c);
        }
        __syncthreads();
        #pragma unroll
        for (int k = 0; k < BK; k++) {
            float ra[TM], rb[TN];
            #pragma unroll
            for (int i = 0; i < TM; i++) ra[i] = As[k][ty * TM + i];
            #pragma unroll
            for (int j = 0; j < TN; j++) rb[j] = Bs[k][tx * TN + j];
            #pragma unroll
            for (int i = 0; i < TM; i++)
                #pragma unroll
                for (int j = 0; j < TN; j++) acc[i][j] += ra[i] * rb[j];
        }
        __syncthreads();
    }
    #pragma unroll
    for (int i = 0; i < TM; i++) {
        int gr = rowBase + ty * TM + i;
        if (gr < M) {
            #pragma unroll
            for (int j = 0; j < TN; j++)
                Cmat[(size_t)gr * NDIM + tx * TN + j] = acc[i][j];
        }
    }
}

// ---------------- per-row dot products: s[i]=h[i].a_src, d[i]=h[i].a_dst ----------------
template <int F>
__global__ void dots_kernel(const float* __restrict__ h, const float* __restrict__ asrc,
                            const float* __restrict__ adst, float* __restrict__ sv,
                            float* __restrict__ dv, int n) {
    int warp = (blockIdx.x * blockDim.x + threadIdx.x) >> 5;
    int lane = threadIdx.x & 31;
    if (warp >= n) return;
    const float* hr = h + (size_t)warp * F;
    float s = 0.f, d = 0.f;
    #pragma unroll
    for (int f = lane; f < F; f += 32) {
        float v = hr[f];
        s += v * asrc[f];
        d += v * adst[f];
    }
    #pragma unroll
    for (int o = 16; o; o >>= 1) {
        s += __shfl_xor_sync(0xffffffffu, s, o);
        d += __shfl_xor_sync(0xffffffffu, d, o);
    }
    if (lane == 0) { sv[warp] = s; dv[warp] = d; }
}

// ---------------- aggregation: out[i] = act( (sum_e softmax * h[src]) + b ) ----------------
// ACT: 0 = relu (layer 1), 1 = sigmoid (layer 2)
template <int F, int ACT>
__global__ void aggregate_kernel(const float* __restrict__ h, const float* __restrict__ sv,
                                 const float* __restrict__ dv, const int* __restrict__ rowptr,
                                 const int* __restrict__ colidx, const float* __restrict__ bias,
                                 float* __restrict__ out, int n) {
    constexpr int FPL = F / 32;
    int warp = (blockIdx.x * blockDim.x + threadIdx.x) >> 5;
    int lane = threadIdx.x & 31;
    if (warp >= n) return;
    int i = warp;
    int start = rowptr[i], end = rowptr[i + 1];
    float di = dv[i];

    // pass 1: max logit
    float m = -INFINITY;
    for (int j = start + lane; j < end; j += 32) {
        float x = sv[colidx[j]] + di;
        x = (x > 0.f) ? x : 0.2f * x;
        m = fmaxf(m, x);
    }
    #pragma unroll
    for (int o = 16; o; o >>= 1) m = fmaxf(m, __shfl_xor_sync(0xffffffffu, m, o));

    // pass 2: weighted accumulation + Z
    float acc[FPL];
    #pragma unroll
    for (int f = 0; f < FPL; f++) acc[f] = 0.f;
    float Z = 0.f;
    for (int j0 = start; j0 < end; j0 += 32) {
        int j = j0 + lane;
        int sn = 0;
        float w = 0.f;
        if (j < end) {
            sn = colidx[j];
            float x = sv[sn] + di;
            x = (x > 0.f) ? x : 0.2f * x;
            w = __expf(x - m);
            Z += w;
        }
        int cnt = min(32, end - j0);
        for (int t = 0; t < cnt; t++) {
            int snb = __shfl_sync(0xffffffffu, sn, t);
            float wb = __shfl_sync(0xffffffffu, w, t);
            const float* hr = h + (size_t)snb * F;
            #pragma unroll
            for (int f = 0; f < FPL; f++) acc[f] += wb * hr[lane + 32 * f];
        }
    }
    #pragma unroll
    for (int o = 16; o; o >>= 1) Z += __shfl_xor_sync(0xffffffffu, Z, o);
    float invZ = 1.f / (Z + 1e-16f);
    #pragma unroll
    for (int f = 0; f < FPL; f++) {
        float v = acc[f] * invZ + bias[lane + 32 * f];
        if (ACT == 0) v = fmaxf(v, 0.f);
        else          v = 1.f / (1.f + __expf(-v));
        out[(size_t)i * F + lane + 32 * f] = v;
    }
}

// ---------------- host launch ----------------
static inline int cdiv(int a, int b) { return (a + b - 1) / b; }

extern "C" void kernel_launch(void* const* d_in, const int* in_sizes, int n_in,
                              void* d_out, int out_size) {
    const int*   ei    = (const int*)d_in[0];
    const float* embed = (const float*)d_in[1];
    const float* W1    = (const float*)d_in[2];
    const float* as1   = (const float*)d_in[3];
    const float* ad1   = (const float*)d_in[4];
    const float* b1    = (const float*)d_in[5];
    const float* W2    = (const float*)d_in[6];
    const float* as2   = (const float*)d_in[7];
    const float* ad2   = (const float*)d_in[8];
    const float* b2    = (const float*)d_in[9];

    int E = in_sizes[0] / 2;
    int N = in_sizes[1] / CDIM;
    const int* srcv = ei;
    const int* dstv = ei + E;

    void* p;
    cudaGetSymbolAddress(&p, g_deg);    int* deg    = (int*)p;
    cudaGetSymbolAddress(&p, g_incl);   int* incl   = (int*)p;
    cudaGetSymbolAddress(&p, g_bsums);  int* bsums  = (int*)p;
    cudaGetSymbolAddress(&p, g_rowptr); int* rowptr = (int*)p;
    cudaGetSymbolAddress(&p, g_pos);    int* pos    = (int*)p;
    cudaGetSymbolAddress(&p, g_col);    int* col    = (int*)p;
    cudaGetSymbolAddress(&p, g_h1);     float* h1   = (float*)p;
    cudaGetSymbolAddress(&p, g_x1);     float* x1   = (float*)p;
    cudaGetSymbolAddress(&p, g_h2);     float* h2   = (float*)p;
    cudaGetSymbolAddress(&p, g_s1);     float* s1   = (float*)p;
    cudaGetSymbolAddress(&p, g_d1);     float* d1   = (float*)p;
    cudaGetSymbolAddress(&p, g_s2);     float* s2   = (float*)p;
    cudaGetSymbolAddress(&p, g_d2);     float* d2   = (float*)p;
    float* out = (float*)d_out;

    int nb = cdiv(N, 1024);

    // CSR build (by destination node), self-loops included
    init_deg_kernel<<<cdiv(N, 256), 256>>>(deg, N);
    hist_kernel<<<cdiv(E, 256), 256>>>(dstv, deg, E);
    scan_block_kernel<<<nb, 1024>>>(deg, incl, bsums, N);
    scan_bsums_kernel<<<1, 32>>>(bsums, nb);
    finalize_rowptr_kernel<<<cdiv(N + 1, 256), 256>>>(incl, bsums, rowptr, N);
    copy_pos_kernel<<<cdiv(N, 256), 256>>>(rowptr, pos, N);
    scatter_kernel<<<cdiv(E, 256), 256>>>(srcv, dstv, pos, col, E);
    selfloop_kernel<<<cdiv(N, 256), 256>>>(pos, col, N);

    // Layer 1: h1 = embed @ W1; s1/d1; aggregate + bias + relu -> x1
    sgemm_kernel<HDIM, CDIM, 8><<<cdiv(N, 128), 256>>>(embed, W1, h1, N);
    dots_kernel<HDIM><<<cdiv(N, 8), 256>>>(h1, as1, ad1, s1, d1, N);
    aggregate_kernel<HDIM, 0><<<cdiv(N, 8), 256>>>(h1, s1, d1, rowptr, col, b1, x1, N);

    // Layer 2: h2 = x1 @ W2; s2/d2; aggregate + bias + sigmoid -> out
    sgemm_kernel<KOUT, HDIM, 4><<<cdiv(N, 128), 256>>>(x1, W2, h2, N);
    dots_kernel<KOUT><<<cdiv(N, 8), 256>>>(h2, as2, ad2, s2, d2, N);
    aggregate_kernel<KOUT, 1><<<cdiv(N, 8), 256>>>(h2, s2, d2, rowptr, col, b2, out, N);
}

// round 2
// speedup vs baseline: 1.7767x; 1.7767x over previous
#include <cuda_runtime.h>
#include <math.h>
#include <stdint.h>

// Problem-fixed shapes: N=100000, C=256, H=128, K=64, E=1600000
#define NN   100000
#define EE   1600000
#define ETOT (EE + NN)
#define CDIM 256
#define HDIM 128
#define KOUT 64

// ---------------- device scratch (static, no allocation) ----------------
__device__ int   g_deg[NN];
__device__ int   g_incl[NN];
__device__ int   g_bsums[256];
__device__ int   g_rowptr[NN + 1];
__device__ int   g_pos[NN];
__device__ int   g_col[ETOT];
__device__ float g_h1[NN * HDIM];
__device__ float g_x1[NN * HDIM];
__device__ float g_h2[NN * KOUT];
__device__ float g_s1[NN], g_d1[NN], g_s2[NN], g_d2[NN];

// ---------------- CSR build ----------------
__global__ void init_deg_kernel(int* deg, int n) {
    int i = blockIdx.x * blockDim.x + threadIdx.x;
    if (i < n) deg[i] = 1;  // self-loop
}

__global__ void hist_kernel(const int* __restrict__ dst, int* deg, int e) {
    int i = blockIdx.x * blockDim.x + threadIdx.x;
    if (i < e) atomicAdd(&deg[dst[i]], 1);
}

__global__ void scan_block_kernel(const int* __restrict__ deg, int* incl, int* bsums, int n) {
    __shared__ int sh[1024];
    int t = threadIdx.x;
    int gid = blockIdx.x * 1024 + t;
    sh[t] = (gid < n) ? deg[gid] : 0;
    __syncthreads();
    #pragma unroll
    for (int off = 1; off < 1024; off <<= 1) {
        int v = (t >= off) ? sh[t - off] : 0;
        __syncthreads();
        sh[t] += v;
        __syncthreads();
    }
    if (gid < n) incl[gid] = sh[t];
    if (t == 1023) bsums[blockIdx.x] = sh[t];
}

// parallel exclusive scan of block sums (nb <= 128)
__global__ void scan_bsums_kernel(int* bsums, int nb) {
    __shared__ int sh[128];
    int t = threadIdx.x;
    sh[t] = (t < nb) ? bsums[t] : 0;
    __syncthreads();
    #pragma unroll
    for (int off = 1; off < 128; off <<= 1) {
        int v = (t >= off) ? sh[t - off] : 0;
        __syncthreads();
        sh[t] += v;
        __syncthreads();
    }
    if (t < nb) bsums[t] = sh[t] - ((t < nb) ? ((t == 0) ? sh[0] : sh[t] - sh[t - 1]) : 0) - (t ? 0 : 0),
    // exclusive = inclusive - own value; own value = sh[t]-sh[t-1] (t>0) or sh[0]
    bsums[t] = (t == 0) ? 0 : sh[t - 1];
}

__global__ void finalize_rowptr_kernel(const int* __restrict__ incl, const int* __restrict__ bsums,
                                       int* rowptr, int n) {
    int gid = blockIdx.x * blockDim.x + threadIdx.x;
    if (gid < n) rowptr[gid + 1] = incl[gid] + bsums[gid >> 10];
    if (gid == 0) rowptr[0] = 0;
}

__global__ void copy_pos_kernel(const int* __restrict__ rowptr, int* pos, int n) {
    int i = blockIdx.x * blockDim.x + threadIdx.x;
    if (i < n) pos[i] = rowptr[i];
}

__global__ void scatter_kernel(const int* __restrict__ srcv, const int* __restrict__ dstv,
                               int* pos, int* colv, int e) {
    int i = blockIdx.x * blockDim.x + threadIdx.x;
    if (i < e) {
        int p = atomicAdd(&pos[dstv[i]], 1);
        colv[p] = srcv[i];
    }
}

__global__ void selfloop_kernel(int* pos, int* colv, int n) {
    int i = blockIdx.x * blockDim.x + threadIdx.x;
    if (i < n) {
        int p = atomicAdd(&pos[i], 1);
        colv[p] = i;
    }
}

// ---------------- tf32 tensor-core GEMM ----------------
// C[M x BN] = A[M x KD] * B[KD x BN], row-major. BN covered by one block column.
// 256 threads = 8 warps in a 2(m) x 4(n) grid; warp tile 64 x (BN/4); BK=32.

__device__ __forceinline__ uint32_t f2tf32(float f) {
    uint32_t r;
    asm("cvt.rna.tf32.f32 %0, %1;" : "=r"(r) : "f"(f));
    return r;
}

template <int BN, int KD>
__global__ __launch_bounds__(256) void mma_gemm_kernel(const float* __restrict__ A,
                                                       const float* __restrict__ B,
                                                       float* __restrict__ Cmat, int M) {
    constexpr int BM = 128, BK = 32;
    constexpr int WN = BN / 4;          // warp n-tile
    constexpr int MT = 4;               // 64/16 m mma-tiles per warp
    constexpr int NT = WN / 8;          // n mma-tiles per warp
    constexpr int AST = BK + 4;         // 36: a-frag reads (4r+c)%32 conflict-free
    constexpr int BST = BN + 8;         // (8k+col)%32 conflict-free

    __shared__ float As[BM][AST];
    __shared__ float Bs[BK][BST];

    int tid = threadIdx.x;
    int lane = tid & 31;
    int wid = tid >> 5;
    int wm = wid & 1;       // 0..1
    int wn = wid >> 1;      // 0..3
    int rowBase = blockIdx.x * BM;

    float acc[MT][NT][4];
    #pragma unroll
    for (int i = 0; i < MT; i++)
        #pragma unroll
        for (int j = 0; j < NT; j++)
            #pragma unroll
            for (int r = 0; r < 4; r++) acc[i][j][r] = 0.f;

    for (int k0 = 0; k0 < KD; k0 += BK) {
        // stage A tile (BM x BK): 1024 float4, 4 per thread
        #pragma unroll
        for (int it = 0; it < 4; it++) {
            int idx = tid + 256 * it;
            int row = idx >> 3;
            int q = idx & 7;
            float4 v = make_float4(0.f, 0.f, 0.f, 0.f);
            int gr = rowBase + row;
            if (gr < M) v = *reinterpret_cast<const float4*>(A + (size_t)gr * KD + k0 + 4 * q);
            float4 w;
            w.x = __uint_as_float(f2tf32(v.x));
            w.y = __uint_as_float(f2tf32(v.y));
            w.z = __uint_as_float(f2tf32(v.z));
            w.w = __uint_as_float(f2tf32(v.w));
            *reinterpret_cast<float4*>(&As[row][4 * q]) = w;
        }
        // stage B tile (BK x BN)
        constexpr int BQ = BN / 4;              // float4 per B row
        constexpr int BIT = (BK * BQ) / 256;    // f4 per thread (4 or 2)
        #pragma unroll
        for (int it = 0; it < BIT; it++) {
            int idx = tid + 256 * it;
            int row = idx / BQ;
            int q = idx % BQ;
            float4 v = *reinterpret_cast<const float4*>(B + (size_t)(k0 + row) * BN + 4 * q);
            float4 w;
            w.x = __uint_as_float(f2tf32(v.x));
            w.y = __uint_as_float(f2tf32(v.y));
            w.z = __uint_as_float(f2tf32(v.z));
            w.w = __uint_as_float(f2tf32(v.w));
            *reinterpret_cast<float4*>(&Bs[row][4 * q]) = w;
        }
        __syncthreads();

        #pragma unroll
        for (int kk = 0; kk < BK / 8; kk++) {
            uint32_t af[MT][4];
            #pragma unroll
            for (int mt = 0; mt < MT; mt++) {
                int r0 = wm * 64 + mt * 16 + (lane >> 2);
                int c0 = 8 * kk + (lane & 3);
                af[mt][0] = __float_as_uint(As[r0][c0]);
                af[mt][1] = __float_as_uint(As[r0 + 8][c0]);
                af[mt][2] = __float_as_uint(As[r0][c0 + 4]);
                af[mt][3] = __float_as_uint(As[r0 + 8][c0 + 4]);
            }
            uint32_t bf[NT][2];
            #pragma unroll
            for (int nt = 0; nt < NT; nt++) {
                int col = wn * WN + nt * 8 + (lane >> 2);
                int kr = 8 * kk + (lane & 3);
                bf[nt][0] = __float_as_uint(Bs[kr][col]);
                bf[nt][1] = __float_as_uint(Bs[kr + 4][col]);
            }
            #pragma unroll
            for (int mt = 0; mt < MT; mt++)
                #pragma unroll
                for (int nt = 0; nt < NT; nt++) {
                    asm volatile(
                        "mma.sync.aligned.m16n8k8.row.col.f32.tf32.tf32.f32 "
                        "{%0,%1,%2,%3}, {%4,%5,%6,%7}, {%8,%9}, {%0,%1,%2,%3};"
                        : "+f"(acc[mt][nt][0]), "+f"(acc[mt][nt][1]),
                          "+f"(acc[mt][nt][2]), "+f"(acc[mt][nt][3])
                        : "r"(af[mt][0]), "r"(af[mt][1]), "r"(af[mt][2]), "r"(af[mt][3]),
                          "r"(bf[nt][0]), "r"(bf[nt][1]));
                }
        }
        __syncthreads();
    }

    // epilogue: float2 stores
    #pragma unroll
    for (int mt = 0; mt < MT; mt++) {
        int r0 = rowBase + wm * 64 + mt * 16 + (lane >> 2);
        #pragma unroll
        for (int nt = 0; nt < NT; nt++) {
            int col = wn * WN + nt * 8 + 2 * (lane & 3);
            if (r0 < M)
                *reinterpret_cast<float2*>(Cmat + (size_t)r0 * BN + col) =
                    make_float2(acc[mt][nt][0], acc[mt][nt][1]);
            if (r0 + 8 < M)
                *reinterpret_cast<float2*>(Cmat + (size_t)(r0 + 8) * BN + col) =
                    make_float2(acc[mt][nt][2], acc[mt][nt][3]);
        }
    }
}

// ---------------- per-row dot products ----------------
template <int F>
__global__ void dots_kernel(const float* __restrict__ h, const float* __restrict__ asrc,
                            const float* __restrict__ adst, float* __restrict__ sv,
                            float* __restrict__ dv, int n) {
    int warp = (blockIdx.x * blockDim.x + threadIdx.x) >> 5;
    int lane = threadIdx.x & 31;
    if (warp >= n) return;
    const float* hr = h + (size_t)warp * F;
    float s = 0.f, d = 0.f;
    #pragma unroll
    for (int f = lane; f < F; f += 32) {
        float v = hr[f];
        s += v * asrc[f];
        d += v * adst[f];
    }
    #pragma unroll
    for (int o = 16; o; o >>= 1) {
        s += __shfl_xor_sync(0xffffffffu, s, o);
        d += __shfl_xor_sync(0xffffffffu, d, o);
    }
    if (lane == 0) { sv[warp] = s; dv[warp] = d; }
}

// ---------------- aggregation ----------------
template <int F, int ACT>
__global__ void aggregate_kernel(const float* __restrict__ h, const float* __restrict__ sv,
                                 const float* __restrict__ dv, const int* __restrict__ rowptr,
                                 const int* __restrict__ colidx, const float* __restrict__ bias,
                                 float* __restrict__ out, int n) {
    constexpr int FPL = F / 32;
    int warp = (blockIdx.x * blockDim.x + threadIdx.x) >> 5;
    int lane = threadIdx.x & 31;
    if (warp >= n) return;
    int i = warp;
    int start = rowptr[i], end = rowptr[i + 1];
    float di = dv[i];

    float m = -INFINITY;
    for (int j = start + lane; j < end; j += 32) {
        float x = sv[colidx[j]] + di;
        x = (x > 0.f) ? x : 0.2f * x;
        m = fmaxf(m, x);
    }
    #pragma unroll
    for (int o = 16; o; o >>= 1) m = fmaxf(m, __shfl_xor_sync(0xffffffffu, m, o));

    float acc[FPL];
    #pragma unroll
    for (int f = 0; f < FPL; f++) acc[f] = 0.f;
    float Z = 0.f;
    for (int j0 = start; j0 < end; j0 += 32) {
        int j = j0 + lane;
        int sn = 0;
        float w = 0.f;
        if (j < end) {
            sn = colidx[j];
            float x = sv[sn] + di;
            x = (x > 0.f) ? x : 0.2f * x;
            w = __expf(x - m);
            Z += w;
        }
        int cnt = min(32, end - j0);
        for (int t = 0; t < cnt; t++) {
            int snb = __shfl_sync(0xffffffffu, sn, t);
            float wb = __shfl_sync(0xffffffffu, w, t);
            const float* hr = h + (size_t)snb * F;
            #pragma unroll
            for (int f = 0; f < FPL; f++) acc[f] += wb * hr[lane + 32 * f];
        }
    }
    #pragma unroll
    for (int o = 16; o; o >>= 1) Z += __shfl_xor_sync(0xffffffffu, Z, o);
    float invZ = 1.f / (Z + 1e-16f);
    #pragma unroll
    for (int f = 0; f < FPL; f++) {
        float v = acc[f] * invZ + bias[lane + 32 * f];
        if (ACT == 0) v = fmaxf(v, 0.f);
        else          v = 1.f / (1.f + __expf(-v));
        out[(size_t)i * F + lane + 32 * f] = v;
    }
}

// ---------------- host launch ----------------
static inline int cdiv(int a, int b) { return (a + b - 1) / b; }

extern "C" void kernel_launch(void* const* d_in, const int* in_sizes, int n_in,
                              void* d_out, int out_size) {
    const int*   ei    = (const int*)d_in[0];
    const float* embed = (const float*)d_in[1];
    const float* W1    = (const float*)d_in[2];
    const float* as1   = (const float*)d_in[3];
    const float* ad1   = (const float*)d_in[4];
    const float* b1    = (const float*)d_in[5];
    const float* W2    = (const float*)d_in[6];
    const float* as2   = (const float*)d_in[7];
    const float* ad2   = (const float*)d_in[8];
    const float* b2    = (const float*)d_in[9];

    int E = in_sizes[0] / 2;
    int N = in_sizes[1] / CDIM;
    const int* srcv = ei;
    const int* dstv = ei + E;

    void* p;
    cudaGetSymbolAddress(&p, g_deg);    int* deg    = (int*)p;
    cudaGetSymbolAddress(&p, g_incl);   int* incl   = (int*)p;
    cudaGetSymbolAddress(&p, g_bsums);  int* bsums  = (int*)p;
    cudaGetSymbolAddress(&p, g_rowptr); int* rowptr = (int*)p;
    cudaGetSymbolAddress(&p, g_pos);    int* pos    = (int*)p;
    cudaGetSymbolAddress(&p, g_col);    int* col    = (int*)p;
    cudaGetSymbolAddress(&p, g_h1);     float* h1   = (float*)p;
    cudaGetSymbolAddress(&p, g_x1);     float* x1   = (float*)p;
    cudaGetSymbolAddress(&p, g_h2);     float* h2   = (float*)p;
    cudaGetSymbolAddress(&p, g_s1);     float* s1   = (float*)p;
    cudaGetSymbolAddress(&p, g_d1);     float* d1   = (float*)p;
    cudaGetSymbolAddress(&p, g_s2);     float* s2   = (float*)p;
    cudaGetSymbolAddress(&p, g_d2);     float* d2   = (float*)p;
    float* out = (float*)d_out;

    int nb = cdiv(N, 1024);

    // CSR build (by destination node), self-loops included
    init_deg_kernel<<<cdiv(N, 256), 256>>>(deg, N);
    hist_kernel<<<cdiv(E, 256), 256>>>(dstv, deg, E);
    scan_block_kernel<<<nb, 1024>>>(deg, incl, bsums, N);
    scan_bsums_kernel<<<1, 128>>>(bsums, nb);
    finalize_rowptr_kernel<<<cdiv(N + 1, 256), 256>>>(incl, bsums, rowptr, N);
    copy_pos_kernel<<<cdiv(N, 256), 256>>>(rowptr, pos, N);
    scatter_kernel<<<cdiv(E, 256), 256>>>(srcv, dstv, pos, col, E);
    selfloop_kernel<<<cdiv(N, 256), 256>>>(pos, col, N);

    // Layer 1
    mma_gemm_kernel<HDIM, CDIM><<<cdiv(N, 128), 256>>>(embed, W1, h1, N);
    dots_kernel<HDIM><<<cdiv(N, 8), 256>>>(h1, as1, ad1, s1, d1, N);
    aggregate_kernel<HDIM, 0><<<cdiv(N, 8), 256>>>(h1, s1, d1, rowptr, col, b1, x1, N);

    // Layer 2
    mma_gemm_kernel<KOUT, HDIM><<<cdiv(N, 128), 256>>>(x1, W2, h2, N);
    dots_kernel<KOUT><<<cdiv(N, 8), 256>>>(h2, as2, ad2, s2, d2, N);
    aggregate_kernel<KOUT, 1><<<cdiv(N, 8), 256>>>(h2, s2, d2, rowptr, col, b2, out, N);
}